// round 1
// baseline (speedup 1.0000x reference)
#include <cuda_runtime.h>

// DynamicTimeStretch: out = (alpha*|s1| + (1-alpha)*|s0|)^2
// Phase accumulation in the reference cancels under abs()^2 — dead code.

#define B_DIM 16
#define N_FREQ 513
#define T_IN 2048
#define N_OUT 2276
#define RATE 0.9f

__global__ void __launch_bounds__(256)
dts_kernel(const float* __restrict__ xr,
           const float* __restrict__ xi,
           float* __restrict__ out)
{
    const int t = blockIdx.x * blockDim.x + threadIdx.x;   // output frame index
    const int row = blockIdx.y;                            // b * N_FREQ + f
    if (t >= N_OUT) return;

    // Match jax f32 arithmetic: time_steps = f32(t) * 0.9f; idx = trunc; alpha = ts - idx
    const float ts = (float)t * RATE;
    const int idx = (int)ts;
    const float a = ts - (float)idx;

    const long base = (long)row * T_IN;
    const float r0 = xr[base + idx];
    const float i0 = xi[base + idx];
    const float n0 = sqrtf(fmaf(r0, r0, i0 * i0));

    float n1 = 0.0f;
    if (idx + 1 < T_IN) {
        const float r1 = xr[base + idx + 1];
        const float i1 = xi[base + idx + 1];
        n1 = sqrtf(fmaf(r1, r1, i1 * i1));
    }

    const float m = fmaf(a, n1, (1.0f - a) * n0);
    out[(long)row * N_OUT + t] = m * m;
}

extern "C" void kernel_launch(void* const* d_in, const int* in_sizes, int n_in,
                              void* d_out, int out_size)
{
    const float* xr = (const float*)d_in[0];
    const float* xi = (const float*)d_in[1];
    float* out = (float*)d_out;

    dim3 block(256, 1, 1);
    dim3 grid((N_OUT + 255) / 256, B_DIM * N_FREQ, 1);
    dts_kernel<<<grid, block>>>(xr, xi, out);
}

// round 2
// speedup vs baseline: 1.8000x; 1.8000x over previous
#include <cuda_runtime.h>

// DynamicTimeStretch: out[t] = (alpha*n[idx+1] + (1-alpha)*n[idx])^2
// where n[j] = |spec[j]|. Phase accumulation cancels under abs()^2.
// One block per (b,f) row: stage norms in shared once, then vectorized consume.

#define B_DIM 16
#define N_FREQ 513
#define T_IN 2048
#define N_OUT 2276
#define N_OUT4 (N_OUT / 4)   // 569
#define RATE 0.9f
#define THREADS 256

__global__ void __launch_bounds__(THREADS)
dts_kernel(const float* __restrict__ xr,
           const float* __restrict__ xi,
           float* __restrict__ out)
{
    __shared__ float n[T_IN + 4];   // +1 sentinel (idx+1 can be 2048), padded

    const int row = blockIdx.x;            // b * N_FREQ + f
    const int tid = threadIdx.x;

    const float4* xr4 = (const float4*)(xr + (long)row * T_IN);
    const float4* xi4 = (const float4*)(xi + (long)row * T_IN);

    // Stage norms: 2048 floats = 512 float4 per input, 2 iters of 256 threads.
    #pragma unroll
    for (int v = 0; v < 2; v++) {
        const int j4 = tid + v * THREADS;          // < 512
        const float4 r = xr4[j4];
        const float4 i = xi4[j4];
        float4 s;
        s.x = sqrtf(fmaf(r.x, r.x, i.x * i.x));
        s.y = sqrtf(fmaf(r.y, r.y, i.y * i.y));
        s.z = sqrtf(fmaf(r.z, r.z, i.z * i.z));
        s.w = sqrtf(fmaf(r.w, r.w, i.w * i.w));
        ((float4*)n)[j4] = s;
    }
    if (tid == 0) n[T_IN] = 0.0f;
    __syncthreads();

    // Consume: 569 float4 outputs, 3 iters (last partial).
    float* out_row = out + (long)row * N_OUT;
    #pragma unroll
    for (int v = 0; v < 3; v++) {
        const int o4 = tid + v * THREADS;
        if (o4 < N_OUT4) {
            float4 res;
            #pragma unroll
            for (int k = 0; k < 4; k++) {
                const int t = o4 * 4 + k;
                // Match jax f32 arithmetic exactly
                const float ts = (float)t * RATE;
                const int idx = (int)ts;
                const float a = ts - (float)idx;
                const float m = fmaf(a, n[idx + 1], (1.0f - a) * n[idx]);
                ((float*)&res)[k] = m * m;
            }
            ((float4*)out_row)[o4] = res;
        }
    }
}

extern "C" void kernel_launch(void* const* d_in, const int* in_sizes, int n_in,
                              void* d_out, int out_size)
{
    const float* xr = (const float*)d_in[0];
    const float* xi = (const float*)d_in[1];
    float* out = (float*)d_out;

    dts_kernel<<<B_DIM * N_FREQ, THREADS>>>(xr, xi, out);
}

// round 3
// speedup vs baseline: 2.0087x; 1.1160x over previous
#include <cuda_runtime.h>

// DynamicTimeStretch: out[t] = (alpha*n[idx+1] + (1-alpha)*n[idx])^2,
// n[j] = |spec[j]|. Phase accumulation cancels under abs()^2.
// 2 rows per block, 384 threads: stage norms to shared, vectorized consume.

#define B_DIM 16
#define N_FREQ 513
#define T_IN 2048
#define N_OUT 2276
#define N_OUT4 (N_OUT / 4)      // 569
#define RATE 0.9f
#define THREADS 384
#define ROWS_PER_BLK 2

__global__ void __launch_bounds__(THREADS)
dts_kernel(const float* __restrict__ xr,
           const float* __restrict__ xi,
           float* __restrict__ out)
{
    __shared__ float n[ROWS_PER_BLK][T_IN + 4];

    const int row0 = blockIdx.x * ROWS_PER_BLK;   // first (b,f) row of this block
    const int tid  = threadIdx.x;

    // ---- Stage: 2 rows * 512 float4 = 1024 work items over 384 threads (3 iters) ----
    // Batch all global loads before the math to maximize MLP.
    float4 r_reg[3], i_reg[3];
    int   j4v[3];
    #pragma unroll
    for (int v = 0; v < 3; v++) {
        const int j4 = tid + v * THREADS;          // flat float4 index in [0,1152)
        j4v[v] = j4;
        if (j4 < 2 * (T_IN / 4)) {
            const int r  = j4 >> 9;                // row within block (512 float4 per row)
            const int lj = j4 & 511;
            const long base4 = ((long)(row0 + r) * T_IN) >> 2;
            r_reg[v] = __ldcs((const float4*)xr + base4 + lj);
            i_reg[v] = __ldcs((const float4*)xi + base4 + lj);
        }
    }
    #pragma unroll
    for (int v = 0; v < 3; v++) {
        const int j4 = j4v[v];
        if (j4 < 2 * (T_IN / 4)) {
            const int r  = j4 >> 9;
            const int lj = j4 & 511;
            const float4 rr = r_reg[v], ii = i_reg[v];
            float4 s;
            s.x = sqrtf(fmaf(rr.x, rr.x, ii.x * ii.x));
            s.y = sqrtf(fmaf(rr.y, rr.y, ii.y * ii.y));
            s.z = sqrtf(fmaf(rr.z, rr.z, ii.z * ii.z));
            s.w = sqrtf(fmaf(rr.w, rr.w, ii.w * ii.w));
            ((float4*)n[r])[lj] = s;
        }
    }
    if (tid < ROWS_PER_BLK) n[tid][T_IN] = 0.0f;   // sentinel: idx+1 can be 2048
    __syncthreads();

    // ---- Consume: 2 rows * 569 float4 = 1138 work items over 384 threads (3 iters) ----
    #pragma unroll
    for (int v = 0; v < 3; v++) {
        const int o = tid + v * THREADS;           // flat output-float4 index
        if (o < ROWS_PER_BLK * N_OUT4) {
            const int r   = (o >= N_OUT4) ? 1 : 0;
            const int o4  = o - r * N_OUT4;
            const float* nr = n[r];
            float4 res;
            #pragma unroll
            for (int k = 0; k < 4; k++) {
                const int t = o4 * 4 + k;
                // Match jax f32 arithmetic exactly
                const float ts = (float)t * RATE;
                const int idx = (int)ts;
                const float a = ts - (float)idx;
                const float m = fmaf(a, nr[idx + 1], (1.0f - a) * nr[idx]);
                ((float*)&res)[k] = m * m;
            }
            __stcs((float4*)(out + (long)(row0 + r) * N_OUT) + o4, res);
        }
    }
}

extern "C" void kernel_launch(void* const* d_in, const int* in_sizes, int n_in,
                              void* d_out, int out_size)
{
    const float* xr = (const float*)d_in[0];
    const float* xi = (const float*)d_in[1];
    float* out = (float*)d_out;

    dts_kernel<<<(B_DIM * N_FREQ) / ROWS_PER_BLK, THREADS>>>(xr, xi, out);
}